// round 10
// baseline (speedup 1.0000x reference)
#include <cuda_runtime.h>
#include <cstdint>

#define NT 256
#define TILE 256      // 8 warps * 32 rows
#define HSTR 132

// ---- smem layout (float offsets) ----
#define OFF_BP1 0                 // 16*4*32*2   = 4096
#define OFF_BP2 4096              // 16*16*32*2  = 16384
#define OFF_BP3 20480             // 2*16*32*2   = 2048
#define OFF_BS0 22528             // 128
#define OFF_BS1 22656             // 128
#define OFF_BS2 22784             // 16
#define OFF_H   22800             // 8 warps * 32 rows * 132 = 33792
#define SMEM_FLOATS (OFF_H + 33792)   // 56592 floats = 226368 B

__device__ __forceinline__ uint32_t cvt_tf32(float f) {
    uint32_t r; asm("cvt.rn.tf32.f32 %0, %1;" : "=r"(r) : "f"(f)); return r;
}
__device__ __forceinline__ float cvt_tf32f(float f) {
    return __uint_as_float(cvt_tf32(f));
}

__device__ __forceinline__ void mma_tf32(float& d0, float& d1, float& d2, float& d3,
                                         uint32_t a0, uint32_t a1, uint32_t a2, uint32_t a3,
                                         uint32_t b0, uint32_t b1) {
    asm("mma.sync.aligned.m16n8k8.row.col.f32.tf32.tf32.f32 "
        "{%0,%1,%2,%3}, {%4,%5,%6,%7}, {%8,%9}, {%0,%1,%2,%3};"
        : "+f"(d0), "+f"(d1), "+f"(d2), "+f"(d3)
        : "r"(a0), "r"(a1), "r"(a2), "r"(a3), "r"(b0), "r"(b1));
}

__device__ __forceinline__ void mat3mul(float* C, const float* A, const float* Bm) {
    #pragma unroll
    for (int i = 0; i < 3; i++)
        #pragma unroll
        for (int j = 0; j < 3; j++)
            C[i*3+j] = A[i*3]*Bm[j] + A[i*3+1]*Bm[3+j] + A[i*3+2]*Bm[6+j];
}

__global__ void __launch_bounds__(NT, 1)
l2t_mma_kernel(const float* __restrict__ y,
               const float* __restrict__ ow0, const float* __restrict__ ob0,
               const float* __restrict__ ow1, const float* __restrict__ ob1,
               const float* __restrict__ ow2, const float* __restrict__ ob2,
               const float* __restrict__ tw0, const float* __restrict__ tb0,
               const float* __restrict__ tw1, const float* __restrict__ tb1,
               const float* __restrict__ tw2, const float* __restrict__ tb2,
               float* __restrict__ out, int tiles)
{
    extern __shared__ float sm[];
    float* Bp1 = sm + OFF_BP1;
    float* Bp2 = sm + OFF_BP2;
    float* Bp3 = sm + OFF_BP3;
    float* bs0 = sm + OFF_BS0;
    float* bs1 = sm + OFF_BS1;
    float* bs2 = sm + OFF_BS2;

    const int tid  = threadIdx.x;
    const int wid  = tid >> 5;
    const int lane = tid & 31;
    const int qr   = lane >> 2;   // 0..7
    const int qc   = lane & 3;    // 0..3
    float* Hw = sm + OFF_H + wid * 32 * HSTR;   // this warp's 32 rows

    #pragma unroll 1
    for (int ph = 0; ph < 2; ++ph) {
        const float* w0 = ph ? tw0 : ow0;  const float* b0 = ph ? tb0 : ob0;
        const float* w1 = ph ? tw1 : ow1;  const float* b1 = ph ? tb1 : ob1;
        const float* w2 = ph ? tw2 : ow2;  const float* b2 = ph ? tb2 : ob2;
        const int nout = ph ? 3 : 9;

        __syncthreads();   // previous phase finished reading packed weights

        // ---- pack weights into B-fragment order (tf32) ----
        for (int i = tid; i < 16*4*32; i += NT) {            // W0 [128][32]
            int l = i & 31, ks = (i >> 5) & 3, nt = i >> 7;
            int n = nt*8 + (l >> 2), k = ks*8 + (l & 3);
            Bp1[i*2+0] = cvt_tf32f(w0[n*32 + k]);
            Bp1[i*2+1] = cvt_tf32f(w0[n*32 + k + 4]);
        }
        for (int i = tid; i < 16*16*32; i += NT) {           // W1 [128][128]
            int l = i & 31, ks = (i >> 5) & 15, nt = i >> 9;
            int n = nt*8 + (l >> 2), k = ks*8 + (l & 3);
            Bp2[i*2+0] = cvt_tf32f(w1[n*128 + k]);
            Bp2[i*2+1] = cvt_tf32f(w1[n*128 + k + 4]);
        }
        for (int i = tid; i < 2*16*32; i += NT) {            // W2 [nout][128], N pad 16
            int l = i & 31, ks = (i >> 5) & 15, nt = i >> 9;
            int n = nt*8 + (l >> 2), k = ks*8 + (l & 3);
            float v0 = (n < nout) ? w2[n*128 + k]     : 0.f;
            float v1 = (n < nout) ? w2[n*128 + k + 4] : 0.f;
            Bp3[i*2+0] = cvt_tf32f(v0);
            Bp3[i*2+1] = cvt_tf32f(v1);
        }
        if (tid < 128) { bs0[tid] = b0[tid]; bs1[tid] = b1[tid]; }
        if (tid < 16)  bs2[tid] = (tid < nout) ? b2[tid] : 0.f;
        __syncthreads();

        #pragma unroll 1
        for (int t = blockIdx.x; t < tiles; t += gridDim.x) {
            const int m0 = t * TILE + wid * 32;   // this warp's 32 rows

            // ---- Layer 1: A from gmem (two 16-row groups, K=32) ----
            uint32_t A1[2][4][4];
            #pragma unroll
            for (int g = 0; g < 2; ++g) {
                const float* yb = y + (size_t)(m0 + g*16 + qr) * 64 + ph * 32 + qc;
                #pragma unroll
                for (int ks = 0; ks < 4; ++ks) {
                    A1[g][ks][0] = cvt_tf32(__ldg(yb + ks*8));
                    A1[g][ks][1] = cvt_tf32(__ldg(yb + 512 + ks*8));
                    A1[g][ks][2] = cvt_tf32(__ldg(yb + ks*8 + 4));
                    A1[g][ks][3] = cvt_tf32(__ldg(yb + 512 + ks*8 + 4));
                }
            }
            #pragma unroll
            for (int nt = 0; nt < 16; ++nt) {
                float d[2][4] = {{0.f,0.f,0.f,0.f},{0.f,0.f,0.f,0.f}};
                #pragma unroll
                for (int ks = 0; ks < 4; ++ks) {
                    float2 bb = *(const float2*)(Bp1 + ((nt*4 + ks)*32 + lane)*2);
                    uint32_t b0r = __float_as_uint(bb.x), b1r = __float_as_uint(bb.y);
                    mma_tf32(d[0][0], d[0][1], d[0][2], d[0][3],
                             A1[0][ks][0], A1[0][ks][1], A1[0][ks][2], A1[0][ks][3], b0r, b1r);
                    mma_tf32(d[1][0], d[1][1], d[1][2], d[1][3],
                             A1[1][ks][0], A1[1][ks][1], A1[1][ks][2], A1[1][ks][3], b0r, b1r);
                }
                const int col = nt*8 + 2*qc;
                const float bv0 = bs0[col], bv1 = bs0[col+1];
                #pragma unroll
                for (int g = 0; g < 2; ++g) {
                    float2 lo, hi;
                    lo.x = cvt_tf32f(fmaxf(d[g][0] + bv0, 0.f));
                    lo.y = cvt_tf32f(fmaxf(d[g][1] + bv1, 0.f));
                    hi.x = cvt_tf32f(fmaxf(d[g][2] + bv0, 0.f));
                    hi.y = cvt_tf32f(fmaxf(d[g][3] + bv1, 0.f));
                    *(float2*)(Hw + (g*16 + qr)*HSTR + col)     = lo;
                    *(float2*)(Hw + (g*16 + qr + 8)*HSTR + col) = hi;
                }
            }
            __syncwarp();

            // ---- Layer 2: A from Hw (K=128), in-place output ----
            uint32_t Ar[2][16][4];
            #pragma unroll
            for (int g = 0; g < 2; ++g)
                #pragma unroll
                for (int ks = 0; ks < 16; ++ks) {
                    Ar[g][ks][0] = __float_as_uint(Hw[(g*16 + qr)*HSTR + ks*8 + qc]);
                    Ar[g][ks][1] = __float_as_uint(Hw[(g*16 + qr + 8)*HSTR + ks*8 + qc]);
                    Ar[g][ks][2] = __float_as_uint(Hw[(g*16 + qr)*HSTR + ks*8 + qc + 4]);
                    Ar[g][ks][3] = __float_as_uint(Hw[(g*16 + qr + 8)*HSTR + ks*8 + qc + 4]);
                }
            __syncwarp();
            #pragma unroll
            for (int nt = 0; nt < 16; ++nt) {
                float d[2][4] = {{0.f,0.f,0.f,0.f},{0.f,0.f,0.f,0.f}};
                #pragma unroll
                for (int ks = 0; ks < 16; ++ks) {
                    float2 bb = *(const float2*)(Bp2 + ((nt*16 + ks)*32 + lane)*2);
                    uint32_t b0r = __float_as_uint(bb.x), b1r = __float_as_uint(bb.y);
                    mma_tf32(d[0][0], d[0][1], d[0][2], d[0][3],
                             Ar[0][ks][0], Ar[0][ks][1], Ar[0][ks][2], Ar[0][ks][3], b0r, b1r);
                    mma_tf32(d[1][0], d[1][1], d[1][2], d[1][3],
                             Ar[1][ks][0], Ar[1][ks][1], Ar[1][ks][2], Ar[1][ks][3], b0r, b1r);
                }
                const int col = nt*8 + 2*qc;
                const float bv0 = bs1[col], bv1 = bs1[col+1];
                #pragma unroll
                for (int g = 0; g < 2; ++g) {
                    float2 lo, hi;
                    lo.x = cvt_tf32f(fmaxf(d[g][0] + bv0, 0.f));
                    lo.y = cvt_tf32f(fmaxf(d[g][1] + bv1, 0.f));
                    hi.x = cvt_tf32f(fmaxf(d[g][2] + bv0, 0.f));
                    hi.y = cvt_tf32f(fmaxf(d[g][3] + bv1, 0.f));
                    *(float2*)(Hw + (g*16 + qr)*HSTR + col)     = lo;
                    *(float2*)(Hw + (g*16 + qr + 8)*HSTR + col) = hi;
                }
            }
            __syncwarp();

            // ---- Layer 3: reload A (reuse Ar), N=16 ----
            #pragma unroll
            for (int g = 0; g < 2; ++g)
                #pragma unroll
                for (int ks = 0; ks < 16; ++ks) {
                    Ar[g][ks][0] = __float_as_uint(Hw[(g*16 + qr)*HSTR + ks*8 + qc]);
                    Ar[g][ks][1] = __float_as_uint(Hw[(g*16 + qr + 8)*HSTR + ks*8 + qc]);
                    Ar[g][ks][2] = __float_as_uint(Hw[(g*16 + qr)*HSTR + ks*8 + qc + 4]);
                    Ar[g][ks][3] = __float_as_uint(Hw[(g*16 + qr + 8)*HSTR + ks*8 + qc + 4]);
                }
            __syncwarp();
            #pragma unroll
            for (int nt = 0; nt < 2; ++nt) {
                float d[2][4] = {{0.f,0.f,0.f,0.f},{0.f,0.f,0.f,0.f}};
                #pragma unroll
                for (int ks = 0; ks < 16; ++ks) {
                    float2 bb = *(const float2*)(Bp3 + ((nt*16 + ks)*32 + lane)*2);
                    uint32_t b0r = __float_as_uint(bb.x), b1r = __float_as_uint(bb.y);
                    mma_tf32(d[0][0], d[0][1], d[0][2], d[0][3],
                             Ar[0][ks][0], Ar[0][ks][1], Ar[0][ks][2], Ar[0][ks][3], b0r, b1r);
                    mma_tf32(d[1][0], d[1][1], d[1][2], d[1][3],
                             Ar[1][ks][0], Ar[1][ks][1], Ar[1][ks][2], Ar[1][ks][3], b0r, b1r);
                }
                const int col = nt*8 + 2*qc;
                #pragma unroll
                for (int g = 0; g < 2; ++g) {
                    Hw[(g*16 + qr)*HSTR + col]           = d[g][0] + bs2[col];
                    Hw[(g*16 + qr)*HSTR + col + 1]       = d[g][1] + bs2[col+1];
                    Hw[(g*16 + qr + 8)*HSTR + col]       = d[g][2] + bs2[col];
                    Hw[(g*16 + qr + 8)*HSTR + col + 1]   = d[g][3] + bs2[col+1];
                }
            }
            __syncwarp();

            // ---- epilogue: one row per lane (all 32 lanes) ----
            if (ph == 0) {
                float A[9], T[9], M[9];
                #pragma unroll
                for (int j = 0; j < 9; ++j) A[j] = Hw[lane*HSTR + j];

                float n0 = fabsf(A[0]) + fabsf(A[1]) + fabsf(A[2]);
                float n1 = fabsf(A[3]) + fabsf(A[4]) + fabsf(A[5]);
                float n2 = fabsf(A[6]) + fabsf(A[7]) + fabsf(A[8]);
                float nrm = fmaxf(n0, fmaxf(n1, n2));
                int s = 0;
                if (nrm > 0.25f) {
                    s = (int)ceilf(log2f(nrm * 4.0f));
                    if (s < 0) s = 0;
                    float sc = exp2f(-(float)s);
                    #pragma unroll
                    for (int j = 0; j < 9; ++j) A[j] *= sc;
                }
                #pragma unroll
                for (int j = 0; j < 9; ++j) T[j] = A[j] * (1.0f/12.0f);
                T[0] += 1.f; T[4] += 1.f; T[8] += 1.f;
                #pragma unroll
                for (int jj = 11; jj >= 1; --jj) {
                    mat3mul(M, A, T);
                    float rc = 1.0f / (float)jj;
                    #pragma unroll
                    for (int j = 0; j < 9; ++j) T[j] = M[j] * rc;
                    T[0] += 1.f; T[4] += 1.f; T[8] += 1.f;
                }
                for (int q = 0; q < s; ++q) {
                    mat3mul(M, T, T);
                    #pragma unroll
                    for (int j = 0; j < 9; ++j) T[j] = M[j];
                }
                const size_t row = (size_t)m0 + lane;
                #pragma unroll
                for (int j = 0; j < 9; ++j) out[row*12 + j] = T[j];
            } else {
                const size_t row = (size_t)m0 + lane;
                #pragma unroll
                for (int j = 0; j < 3; ++j)
                    out[row*12 + 9 + j] = Hw[lane*HSTR + j];
            }
            __syncwarp();  // Hw scratch reads done before next tile's layer 1
        }
    }
}

extern "C" void kernel_launch(void* const* d_in, const int* in_sizes, int n_in,
                              void* d_out, int out_size)
{
    const float* y   = (const float*)d_in[0];
    const float* ow0 = (const float*)d_in[1];
    const float* ob0 = (const float*)d_in[2];
    const float* ow1 = (const float*)d_in[3];
    const float* ob1 = (const float*)d_in[4];
    const float* ow2 = (const float*)d_in[5];
    const float* ob2 = (const float*)d_in[6];
    const float* tw0 = (const float*)d_in[7];
    const float* tb0 = (const float*)d_in[8];
    const float* tw1 = (const float*)d_in[9];
    const float* tb1 = (const float*)d_in[10];
    const float* tw2 = (const float*)d_in[11];
    const float* tb2 = (const float*)d_in[12];
    float* out = (float*)d_out;

    const int Bn = in_sizes[0] / 64;
    const int tiles = Bn / TILE;                 // 512 for B=131072

    int sms = 148;
    cudaDeviceGetAttribute(&sms, cudaDevAttrMultiProcessorCount, 0);
    int grid = tiles < sms ? tiles : sms;

    const size_t smem = SMEM_FLOATS * sizeof(float);
    cudaFuncSetAttribute(l2t_mma_kernel, cudaFuncAttributeMaxDynamicSharedMemorySize, (int)smem);
    l2t_mma_kernel<<<grid, NT, smem>>>(y, ow0, ob0, ow1, ob1, ow2, ob2,
                                       tw0, tb0, tw1, tb1, tw2, tb2, out, tiles);
}

// round 15
// speedup vs baseline: 1.7858x; 1.7858x over previous
#include <cuda_runtime.h>
#include <cuda_fp16.h>
#include <cstdint>

#define NT 512
#define WARPS 16
#define TILE 512        // 16 warps * 32 rows
#define HSTR 136        // half-elements stride for H rows (conflict-free)

// ---- smem layout (byte offsets) ----
#define OFF_BP1 0            // 16nt*2kb*32*8B  = 8192
#define OFF_BP2 8192         // 16nt*8kb*32*8B  = 32768
#define OFF_BP3 40960        // 2nt*8kb*32*8B   = 4096
#define OFF_BS0 45056        // 128 f32
#define OFF_BS1 45568        // 128 f32
#define OFF_BS2 46080        // 16 f32
#define OFF_H   46144        // 16 warps * 32 rows * 136 halves * 2B = 139264
#define SMEM_BYTES (OFF_H + 139264)   // 185408

__device__ __forceinline__ uint32_t pack_h2(float a, float b) {
    __half2 h = __floats2half2_rn(a, b);
    return *(uint32_t*)&h;
}

__device__ __forceinline__ void mma_f16(float& d0, float& d1, float& d2, float& d3,
                                        uint32_t a0, uint32_t a1, uint32_t a2, uint32_t a3,
                                        uint32_t b0, uint32_t b1) {
    asm("mma.sync.aligned.m16n8k16.row.col.f32.f16.f16.f32 "
        "{%0,%1,%2,%3}, {%4,%5,%6,%7}, {%8,%9}, {%0,%1,%2,%3};"
        : "+f"(d0), "+f"(d1), "+f"(d2), "+f"(d3)
        : "r"(a0), "r"(a1), "r"(a2), "r"(a3), "r"(b0), "r"(b1));
}

__device__ __forceinline__ void mat3mul(float* C, const float* A, const float* Bm) {
    #pragma unroll
    for (int i = 0; i < 3; i++)
        #pragma unroll
        for (int j = 0; j < 3; j++)
            C[i*3+j] = A[i*3]*Bm[j] + A[i*3+1]*Bm[3+j] + A[i*3+2]*Bm[6+j];
}

__global__ void __launch_bounds__(NT, 1)
l2t_h_kernel(const float* __restrict__ y,
             const float* __restrict__ ow0, const float* __restrict__ ob0,
             const float* __restrict__ ow1, const float* __restrict__ ob1,
             const float* __restrict__ ow2, const float* __restrict__ ob2,
             const float* __restrict__ tw0, const float* __restrict__ tb0,
             const float* __restrict__ tw1, const float* __restrict__ tb1,
             const float* __restrict__ tw2, const float* __restrict__ tb2,
             float* __restrict__ out, int tiles)
{
    extern __shared__ char smc[];
    uint2* Bp1 = (uint2*)(smc + OFF_BP1);
    uint2* Bp2 = (uint2*)(smc + OFF_BP2);
    uint2* Bp3 = (uint2*)(smc + OFF_BP3);
    float* bs0 = (float*)(smc + OFF_BS0);
    float* bs1 = (float*)(smc + OFF_BS1);
    float* bs2 = (float*)(smc + OFF_BS2);

    const int tid  = threadIdx.x;
    const int wid  = tid >> 5;
    const int lane = tid & 31;
    const int qr   = lane >> 2;   // 0..7
    const int qc   = lane & 3;    // 0..3
    __half* Hw = (__half*)(smc + OFF_H) + wid * 32 * HSTR;   // warp's 32 rows
    float*  Sw = (float*)Hw;                                  // f32 scratch (layer-3 out)

    #pragma unroll 1
    for (int ph = 0; ph < 2; ++ph) {
        const float* w0 = ph ? tw0 : ow0;  const float* b0 = ph ? tb0 : ob0;
        const float* w1 = ph ? tw1 : ow1;  const float* b1 = ph ? tb1 : ob1;
        const float* w2 = ph ? tw2 : ow2;  const float* b2 = ph ? tb2 : ob2;
        const int nout = ph ? 3 : 9;

        __syncthreads();   // previous phase fully done with packed weights

        // ---- pack weights into fp16 B-fragment order ----
        // frag lane l: n = nt*8 + (l>>2), k = kb*16 + 2*(l&3)
        for (int i = tid; i < 16*2*32; i += NT) {            // W0 [128][32], KB=2
            int l = i & 31, kb = (i >> 5) & 1, nt = i >> 6;
            int n = nt*8 + (l >> 2), k = kb*16 + 2*(l & 3);
            Bp1[i] = make_uint2(pack_h2(w0[n*32 + k],     w0[n*32 + k + 1]),
                                pack_h2(w0[n*32 + k + 8], w0[n*32 + k + 9]));
        }
        for (int i = tid; i < 16*8*32; i += NT) {            // W1 [128][128], KB=8
            int l = i & 31, kb = (i >> 5) & 7, nt = i >> 8;
            int n = nt*8 + (l >> 2), k = kb*16 + 2*(l & 3);
            Bp2[i] = make_uint2(pack_h2(w1[n*128 + k],     w1[n*128 + k + 1]),
                                pack_h2(w1[n*128 + k + 8], w1[n*128 + k + 9]));
        }
        for (int i = tid; i < 2*8*32; i += NT) {             // W2 [nout][128] pad N16
            int l = i & 31, kb = (i >> 5) & 7, nt = i >> 8;
            int n = nt*8 + (l >> 2), k = kb*16 + 2*(l & 3);
            uint2 v = make_uint2(0u, 0u);
            if (n < nout)
                v = make_uint2(pack_h2(w2[n*128 + k],     w2[n*128 + k + 1]),
                               pack_h2(w2[n*128 + k + 8], w2[n*128 + k + 9]));
            Bp3[i] = v;
        }
        if (tid < 128) { bs0[tid] = b0[tid]; bs1[tid] = b1[tid]; }
        if (tid < 16)  bs2[tid] = (tid < nout) ? b2[tid] : 0.f;
        __syncthreads();

        #pragma unroll 1
        for (int t = blockIdx.x; t < tiles; t += gridDim.x) {
            const int m0 = t * TILE + wid * 32;

            // ---- Layer 1: A from gmem (K=32 -> 2 k16-blocks) ----
            uint32_t A1[2][2][4];
            #pragma unroll
            for (int g = 0; g < 2; ++g) {
                const float* yb = y + (size_t)(m0 + g*16 + qr) * 64 + ph * 32;
                #pragma unroll
                for (int kb = 0; kb < 2; ++kb) {
                    const int base = kb*16 + 2*qc;
                    float2 v0 = __ldg((const float2*)(yb + base));
                    float2 v1 = __ldg((const float2*)(yb + 512 + base));
                    float2 v2 = __ldg((const float2*)(yb + base + 8));
                    float2 v3 = __ldg((const float2*)(yb + 512 + base + 8));
                    A1[g][kb][0] = pack_h2(v0.x, v0.y);
                    A1[g][kb][1] = pack_h2(v1.x, v1.y);
                    A1[g][kb][2] = pack_h2(v2.x, v2.y);
                    A1[g][kb][3] = pack_h2(v3.x, v3.y);
                }
            }
            #pragma unroll
            for (int nt = 0; nt < 16; ++nt) {
                float d[2][4] = {{0.f,0.f,0.f,0.f},{0.f,0.f,0.f,0.f}};
                #pragma unroll
                for (int kb = 0; kb < 2; ++kb) {
                    uint2 bb = Bp1[(nt*2 + kb)*32 + lane];
                    mma_f16(d[0][0], d[0][1], d[0][2], d[0][3],
                            A1[0][kb][0], A1[0][kb][1], A1[0][kb][2], A1[0][kb][3], bb.x, bb.y);
                    mma_f16(d[1][0], d[1][1], d[1][2], d[1][3],
                            A1[1][kb][0], A1[1][kb][1], A1[1][kb][2], A1[1][kb][3], bb.x, bb.y);
                }
                const int col = nt*8 + 2*qc;
                const float bv0 = bs0[col], bv1 = bs0[col+1];
                #pragma unroll
                for (int g = 0; g < 2; ++g) {
                    *(uint32_t*)(Hw + (g*16 + qr)*HSTR + col) =
                        pack_h2(fmaxf(d[g][0] + bv0, 0.f), fmaxf(d[g][1] + bv1, 0.f));
                    *(uint32_t*)(Hw + (g*16 + qr + 8)*HSTR + col) =
                        pack_h2(fmaxf(d[g][2] + bv0, 0.f), fmaxf(d[g][3] + bv1, 0.f));
                }
            }
            __syncwarp();

            // ---- Layer 2: A from Hw (K=128 -> 8 k16-blocks), in-place ----
            uint32_t Ar[2][8][4];
            #pragma unroll
            for (int g = 0; g < 2; ++g)
                #pragma unroll
                for (int kb = 0; kb < 8; ++kb) {
                    const __half* hr = Hw + (g*16 + qr)*HSTR + kb*16 + 2*qc;
                    Ar[g][kb][0] = *(const uint32_t*)(hr);
                    Ar[g][kb][1] = *(const uint32_t*)(hr + 8*HSTR);
                    Ar[g][kb][2] = *(const uint32_t*)(hr + 8);
                    Ar[g][kb][3] = *(const uint32_t*)(hr + 8*HSTR + 8);
                }
            __syncwarp();
            #pragma unroll
            for (int nt = 0; nt < 16; ++nt) {
                float d[2][4] = {{0.f,0.f,0.f,0.f},{0.f,0.f,0.f,0.f}};
                #pragma unroll
                for (int kb = 0; kb < 8; ++kb) {
                    uint2 bb = Bp2[(nt*8 + kb)*32 + lane];
                    mma_f16(d[0][0], d[0][1], d[0][2], d[0][3],
                            Ar[0][kb][0], Ar[0][kb][1], Ar[0][kb][2], Ar[0][kb][3], bb.x, bb.y);
                    mma_f16(d[1][0], d[1][1], d[1][2], d[1][3],
                            Ar[1][kb][0], Ar[1][kb][1], Ar[1][kb][2], Ar[1][kb][3], bb.x, bb.y);
                }
                const int col = nt*8 + 2*qc;
                const float bv0 = bs1[col], bv1 = bs1[col+1];
                #pragma unroll
                for (int g = 0; g < 2; ++g) {
                    *(uint32_t*)(Hw + (g*16 + qr)*HSTR + col) =
                        pack_h2(fmaxf(d[g][0] + bv0, 0.f), fmaxf(d[g][1] + bv1, 0.f));
                    *(uint32_t*)(Hw + (g*16 + qr + 8)*HSTR + col) =
                        pack_h2(fmaxf(d[g][2] + bv0, 0.f), fmaxf(d[g][3] + bv1, 0.f));
                }
            }
            __syncwarp();

            // ---- Layer 3: reload A (reuse Ar), N=16 pad ----
            #pragma unroll
            for (int g = 0; g < 2; ++g)
                #pragma unroll
                for (int kb = 0; kb < 8; ++kb) {
                    const __half* hr = Hw + (g*16 + qr)*HSTR + kb*16 + 2*qc;
                    Ar[g][kb][0] = *(const uint32_t*)(hr);
                    Ar[g][kb][1] = *(const uint32_t*)(hr + 8*HSTR);
                    Ar[g][kb][2] = *(const uint32_t*)(hr + 8);
                    Ar[g][kb][3] = *(const uint32_t*)(hr + 8*HSTR + 8);
                }
            __syncwarp();
            const int ntmax = ph ? 1 : 2;
            #pragma unroll
            for (int nt = 0; nt < 2; ++nt) {
                if (nt >= ntmax) break;
                float d[2][4] = {{0.f,0.f,0.f,0.f},{0.f,0.f,0.f,0.f}};
                #pragma unroll
                for (int kb = 0; kb < 8; ++kb) {
                    uint2 bb = Bp3[(nt*8 + kb)*32 + lane];
                    mma_f16(d[0][0], d[0][1], d[0][2], d[0][3],
                            Ar[0][kb][0], Ar[0][kb][1], Ar[0][kb][2], Ar[0][kb][3], bb.x, bb.y);
                    mma_f16(d[1][0], d[1][1], d[1][2], d[1][3],
                            Ar[1][kb][0], Ar[1][kb][1], Ar[1][kb][2], Ar[1][kb][3], bb.x, bb.y);
                }
                const int col = nt*8 + 2*qc;
                #pragma unroll
                for (int g = 0; g < 2; ++g) {
                    Sw[(g*16 + qr)*20 + col]         = d[g][0] + bs2[col];
                    Sw[(g*16 + qr)*20 + col + 1]     = d[g][1] + bs2[col+1];
                    Sw[(g*16 + qr + 8)*20 + col]     = d[g][2] + bs2[col];
                    Sw[(g*16 + qr + 8)*20 + col + 1] = d[g][3] + bs2[col+1];
                }
            }
            __syncwarp();

            // ---- epilogue: one row per lane ----
            if (ph == 0) {
                float A[9], T[9], M[9];
                #pragma unroll
                for (int j = 0; j < 9; ++j) A[j] = Sw[lane*20 + j];

                float n0 = fabsf(A[0]) + fabsf(A[1]) + fabsf(A[2]);
                float n1 = fabsf(A[3]) + fabsf(A[4]) + fabsf(A[5]);
                float n2 = fabsf(A[6]) + fabsf(A[7]) + fabsf(A[8]);
                float nrm = fmaxf(n0, fmaxf(n1, n2));
                int s = 0;
                if (nrm > 0.25f) {
                    s = (int)ceilf(log2f(nrm * 4.0f));
                    if (s < 0) s = 0;
                    float sc = exp2f(-(float)s);
                    #pragma unroll
                    for (int j = 0; j < 9; ++j) A[j] *= sc;
                }
                #pragma unroll
                for (int j = 0; j < 9; ++j) T[j] = A[j] * (1.0f/12.0f);
                T[0] += 1.f; T[4] += 1.f; T[8] += 1.f;
                #pragma unroll
                for (int jj = 11; jj >= 1; --jj) {
                    mat3mul(M, A, T);
                    float rc = 1.0f / (float)jj;
                    #pragma unroll
                    for (int j = 0; j < 9; ++j) T[j] = M[j] * rc;
                    T[0] += 1.f; T[4] += 1.f; T[8] += 1.f;
                }
                for (int q = 0; q < s; ++q) {
                    mat3mul(M, T, T);
                    #pragma unroll
                    for (int j = 0; j < 9; ++j) T[j] = M[j];
                }
                const size_t row = (size_t)m0 + lane;
                #pragma unroll
                for (int j = 0; j < 9; ++j) out[row*12 + j] = T[j];
            } else {
                const size_t row = (size_t)m0 + lane;
                #pragma unroll
                for (int j = 0; j < 3; ++j)
                    out[row*12 + 9 + j] = Sw[lane*20 + j];
            }
            __syncwarp();  // scratch reads done before next tile overwrites Hw
        }
    }
}

extern "C" void kernel_launch(void* const* d_in, const int* in_sizes, int n_in,
                              void* d_out, int out_size)
{
    const float* y   = (const float*)d_in[0];
    const float* ow0 = (const float*)d_in[1];
    const float* ob0 = (const float*)d_in[2];
    const float* ow1 = (const float*)d_in[3];
    const float* ob1 = (const float*)d_in[4];
    const float* ow2 = (const float*)d_in[5];
    const float* ob2 = (const float*)d_in[6];
    const float* tw0 = (const float*)d_in[7];
    const float* tb0 = (const float*)d_in[8];
    const float* tw1 = (const float*)d_in[9];
    const float* tb1 = (const float*)d_in[10];
    const float* tw2 = (const float*)d_in[11];
    const float* tb2 = (const float*)d_in[12];
    float* out = (float*)d_out;

    const int Bn = in_sizes[0] / 64;
    const int tiles = Bn / TILE;                 // 256 for B=131072

    int sms = 148;
    cudaDeviceGetAttribute(&sms, cudaDevAttrMultiProcessorCount, 0);
    int grid = tiles < sms ? tiles : sms;

    cudaFuncSetAttribute(l2t_h_kernel, cudaFuncAttributeMaxDynamicSharedMemorySize, SMEM_BYTES);
    l2t_h_kernel<<<grid, NT, SMEM_BYTES>>>(y, ow0, ob0, ow1, ob1, ow2, ob2,
                                           tw0, tb0, tw1, tb1, tw2, tb2, out, tiles);
}

// round 16
// speedup vs baseline: 1.9136x; 1.0716x over previous
#include <cuda_runtime.h>
#include <cuda_fp16.h>
#include <cstdint>

#define NT 512
#define TILE 512        // 16 warps * 32 rows
#define SSTR 21         // f32 scratch stride (conflict-free: gcd(21,32)=1)

// ---- smem layout (byte offsets) ----
#define OFF_BP1 0            // 16nt*2kb*32*8B  = 8192
#define OFF_BP2 8192         // 16nt*8kb*32*8B  = 32768
#define OFF_BP3 40960        // 2nt*8kb*32*8B   = 4096
#define OFF_BS0 45056        // 128 f32
#define OFF_BS1 45568        // 128 f32
#define OFF_BS2 46080        // 16 f32
#define OFF_S   46144        // 16 warps * 32 rows * 21 f32 * 4B = 43008
#define SMEM_BYTES (OFF_S + 43008)   // 89152

__device__ __forceinline__ uint32_t pack_h2(float a, float b) {
    __half2 h = __floats2half2_rn(a, b);
    return *(uint32_t*)&h;
}

__device__ __forceinline__ void mma_f16(float& d0, float& d1, float& d2, float& d3,
                                        uint32_t a0, uint32_t a1, uint32_t a2, uint32_t a3,
                                        uint32_t b0, uint32_t b1) {
    asm("mma.sync.aligned.m16n8k16.row.col.f32.f16.f16.f32 "
        "{%0,%1,%2,%3}, {%4,%5,%6,%7}, {%8,%9}, {%0,%1,%2,%3};"
        : "+f"(d0), "+f"(d1), "+f"(d2), "+f"(d3)
        : "r"(a0), "r"(a1), "r"(a2), "r"(a3), "r"(b0), "r"(b1));
}

__device__ __forceinline__ void mat3mul(float* C, const float* A, const float* Bm) {
    #pragma unroll
    for (int i = 0; i < 3; i++)
        #pragma unroll
        for (int j = 0; j < 3; j++)
            C[i*3+j] = A[i*3]*Bm[j] + A[i*3+1]*Bm[3+j] + A[i*3+2]*Bm[6+j];
}

__global__ void __launch_bounds__(NT, 1)
l2t_reg_kernel(const float* __restrict__ y,
               const float* __restrict__ ow0, const float* __restrict__ ob0,
               const float* __restrict__ ow1, const float* __restrict__ ob1,
               const float* __restrict__ ow2, const float* __restrict__ ob2,
               const float* __restrict__ tw0, const float* __restrict__ tb0,
               const float* __restrict__ tw1, const float* __restrict__ tb1,
               const float* __restrict__ tw2, const float* __restrict__ tb2,
               float* __restrict__ out, int tiles)
{
    extern __shared__ char smc[];
    uint2* Bp1 = (uint2*)(smc + OFF_BP1);
    uint2* Bp2 = (uint2*)(smc + OFF_BP2);
    uint2* Bp3 = (uint2*)(smc + OFF_BP3);
    float* bs0 = (float*)(smc + OFF_BS0);
    float* bs1 = (float*)(smc + OFF_BS1);
    float* bs2 = (float*)(smc + OFF_BS2);

    const int tid  = threadIdx.x;
    const int wid  = tid >> 5;
    const int lane = tid & 31;
    const int qr   = lane >> 2;   // 0..7
    const int qc   = lane & 3;    // 0..3
    float* Sw = (float*)(smc + OFF_S) + wid * 32 * SSTR;

    #pragma unroll 1
    for (int ph = 0; ph < 2; ++ph) {
        const float* w0 = ph ? tw0 : ow0;  const float* b0 = ph ? tb0 : ob0;
        const float* w1 = ph ? tw1 : ow1;  const float* b1 = ph ? tb1 : ob1;
        const float* w2 = ph ? tw2 : ow2;  const float* b2 = ph ? tb2 : ob2;
        const int nout = ph ? 3 : 9;

        __syncthreads();   // previous phase fully done with packed weights

        // ---- pack weights into fp16 B-fragment order ----
        // frag lane l: n = nt*8 + (l>>2), k = kb*16 + 2*(l&3)
        for (int i = tid; i < 16*2*32; i += NT) {            // W0 [128][32], KB=2
            int l = i & 31, kb = (i >> 5) & 1, nt = i >> 6;
            int n = nt*8 + (l >> 2), k = kb*16 + 2*(l & 3);
            Bp1[i] = make_uint2(pack_h2(w0[n*32 + k],     w0[n*32 + k + 1]),
                                pack_h2(w0[n*32 + k + 8], w0[n*32 + k + 9]));
        }
        for (int i = tid; i < 16*8*32; i += NT) {            // W1 [128][128], KB=8
            int l = i & 31, kb = (i >> 5) & 7, nt = i >> 8;
            int n = nt*8 + (l >> 2), k = kb*16 + 2*(l & 3);
            Bp2[i] = make_uint2(pack_h2(w1[n*128 + k],     w1[n*128 + k + 1]),
                                pack_h2(w1[n*128 + k + 8], w1[n*128 + k + 9]));
        }
        for (int i = tid; i < 2*8*32; i += NT) {             // W2 [nout][128] pad N16
            int l = i & 31, kb = (i >> 5) & 7, nt = i >> 8;
            int n = nt*8 + (l >> 2), k = kb*16 + 2*(l & 3);
            uint2 v = make_uint2(0u, 0u);
            if (n < nout)
                v = make_uint2(pack_h2(w2[n*128 + k],     w2[n*128 + k + 1]),
                               pack_h2(w2[n*128 + k + 8], w2[n*128 + k + 9]));
            Bp3[i] = v;
        }
        if (tid < 128) { bs0[tid] = b0[tid]; bs1[tid] = b1[tid]; }
        if (tid < 16)  bs2[tid] = (tid < nout) ? b2[tid] : 0.f;
        __syncthreads();

        #pragma unroll 1
        for (int t = blockIdx.x; t < tiles; t += gridDim.x) {
            const int m0 = t * TILE + wid * 32;

            // ---- Layer 1: A from gmem (K=32 -> 2 k16-blocks) ----
            uint32_t A1[2][2][4];
            #pragma unroll
            for (int g = 0; g < 2; ++g) {
                const float* yb = y + (size_t)(m0 + g*16 + qr) * 64 + ph * 32;
                #pragma unroll
                for (int kb = 0; kb < 2; ++kb) {
                    const int base = kb*16 + 2*qc;
                    float2 v0 = __ldg((const float2*)(yb + base));
                    float2 v1 = __ldg((const float2*)(yb + 512 + base));
                    float2 v2 = __ldg((const float2*)(yb + base + 8));
                    float2 v3 = __ldg((const float2*)(yb + 512 + base + 8));
                    A1[g][kb][0] = pack_h2(v0.x, v0.y);
                    A1[g][kb][1] = pack_h2(v1.x, v1.y);
                    A1[g][kb][2] = pack_h2(v2.x, v2.y);
                    A1[g][kb][3] = pack_h2(v3.x, v3.y);
                }
            }

            // Layer 1 -> A2 fragments directly in registers
            uint32_t A2[2][8][4];
            #pragma unroll
            for (int nt = 0; nt < 16; ++nt) {
                float d[2][4] = {{0.f,0.f,0.f,0.f},{0.f,0.f,0.f,0.f}};
                #pragma unroll
                for (int kb = 0; kb < 2; ++kb) {
                    uint2 bb = Bp1[(nt*2 + kb)*32 + lane];
                    mma_f16(d[0][0], d[0][1], d[0][2], d[0][3],
                            A1[0][kb][0], A1[0][kb][1], A1[0][kb][2], A1[0][kb][3], bb.x, bb.y);
                    mma_f16(d[1][0], d[1][1], d[1][2], d[1][3],
                            A1[1][kb][0], A1[1][kb][1], A1[1][kb][2], A1[1][kb][3], bb.x, bb.y);
                }
                const int col = nt*8 + 2*qc;
                const float bv0 = bs0[col], bv1 = bs0[col+1];
                const int kb2 = nt >> 1;
                const int s01 = (nt & 1) ? 2 : 0;   // a0/a1 (even nt) or a2/a3 (odd nt)
                #pragma unroll
                for (int g = 0; g < 2; ++g) {
                    A2[g][kb2][s01]     = pack_h2(fmaxf(d[g][0] + bv0, 0.f),
                                                  fmaxf(d[g][1] + bv1, 0.f));
                    A2[g][kb2][s01 + 1] = pack_h2(fmaxf(d[g][2] + bv0, 0.f),
                                                  fmaxf(d[g][3] + bv1, 0.f));
                }
            }

            // ---- Layer 2 with fused Layer 3 (register-resident) ----
            float D3[2][2][4] = {};   // [nt3][g][..]
            uint32_t A3[2][4];
            const int ntmax3 = ph ? 1 : 2;
            #pragma unroll
            for (int nt = 0; nt < 16; ++nt) {
                float d[2][4] = {{0.f,0.f,0.f,0.f},{0.f,0.f,0.f,0.f}};
                #pragma unroll
                for (int kb = 0; kb < 8; ++kb) {
                    uint2 bb = Bp2[(nt*8 + kb)*32 + lane];
                    mma_f16(d[0][0], d[0][1], d[0][2], d[0][3],
                            A2[0][kb][0], A2[0][kb][1], A2[0][kb][2], A2[0][kb][3], bb.x, bb.y);
                    mma_f16(d[1][0], d[1][1], d[1][2], d[1][3],
                            A2[1][kb][0], A2[1][kb][1], A2[1][kb][2], A2[1][kb][3], bb.x, bb.y);
                }
                const int col = nt*8 + 2*qc;
                const float bv0 = bs1[col], bv1 = bs1[col+1];
                const int s01 = (nt & 1) ? 2 : 0;
                #pragma unroll
                for (int g = 0; g < 2; ++g) {
                    A3[g][s01]     = pack_h2(fmaxf(d[g][0] + bv0, 0.f),
                                             fmaxf(d[g][1] + bv1, 0.f));
                    A3[g][s01 + 1] = pack_h2(fmaxf(d[g][2] + bv0, 0.f),
                                             fmaxf(d[g][3] + bv1, 0.f));
                }
                if (nt & 1) {                      // A3 for kb2 complete -> consume now
                    const int kb2 = nt >> 1;
                    #pragma unroll
                    for (int nt3 = 0; nt3 < 2; ++nt3) {
                        if (nt3 >= ntmax3) break;
                        uint2 bb = Bp3[(nt3*8 + kb2)*32 + lane];
                        mma_f16(D3[nt3][0][0], D3[nt3][0][1], D3[nt3][0][2], D3[nt3][0][3],
                                A3[0][0], A3[0][1], A3[0][2], A3[0][3], bb.x, bb.y);
                        mma_f16(D3[nt3][1][0], D3[nt3][1][1], D3[nt3][1][2], D3[nt3][1][3],
                                A3[1][0], A3[1][1], A3[1][2], A3[1][3], bb.x, bb.y);
                    }
                }
            }

            // ---- scatter D3 (+bias) to scratch for row-major gather ----
            #pragma unroll
            for (int nt3 = 0; nt3 < 2; ++nt3) {
                if (nt3 >= ntmax3) break;
                const int col = nt3*8 + 2*qc;
                const float bv0 = bs2[col], bv1 = bs2[col+1];
                #pragma unroll
                for (int g = 0; g < 2; ++g) {
                    Sw[(g*16 + qr)*SSTR + col]         = D3[nt3][g][0] + bv0;
                    Sw[(g*16 + qr)*SSTR + col + 1]     = D3[nt3][g][1] + bv1;
                    Sw[(g*16 + qr + 8)*SSTR + col]     = D3[nt3][g][2] + bv0;
                    Sw[(g*16 + qr + 8)*SSTR + col + 1] = D3[nt3][g][3] + bv1;
                }
            }
            __syncwarp();

            // ---- epilogue: one row per lane ----
            if (ph == 0) {
                float A[9], T[9], M[9];
                #pragma unroll
                for (int j = 0; j < 9; ++j) A[j] = Sw[lane*SSTR + j];

                float n0 = fabsf(A[0]) + fabsf(A[1]) + fabsf(A[2]);
                float n1 = fabsf(A[3]) + fabsf(A[4]) + fabsf(A[5]);
                float n2 = fabsf(A[6]) + fabsf(A[7]) + fabsf(A[8]);
                float nrm = fmaxf(n0, fmaxf(n1, n2));
                int s = 0;
                if (nrm > 0.25f) {
                    s = (int)ceilf(log2f(nrm * 4.0f));
                    if (s < 0) s = 0;
                    float sc = exp2f(-(float)s);
                    #pragma unroll
                    for (int j = 0; j < 9; ++j) A[j] *= sc;
                }
                #pragma unroll
                for (int j = 0; j < 9; ++j) T[j] = A[j] * (1.0f/12.0f);
                T[0] += 1.f; T[4] += 1.f; T[8] += 1.f;
                #pragma unroll
                for (int jj = 11; jj >= 1; --jj) {
                    mat3mul(M, A, T);
                    float rc = 1.0f / (float)jj;
                    #pragma unroll
                    for (int j = 0; j < 9; ++j) T[j] = M[j] * rc;
                    T[0] += 1.f; T[4] += 1.f; T[8] += 1.f;
                }
                for (int q = 0; q < s; ++q) {
                    mat3mul(M, T, T);
                    #pragma unroll
                    for (int j = 0; j < 9; ++j) T[j] = M[j];
                }
                const size_t row = (size_t)m0 + lane;
                #pragma unroll
                for (int j = 0; j < 9; ++j) out[row*12 + j] = T[j];
            } else {
                const size_t row = (size_t)m0 + lane;
                #pragma unroll
                for (int j = 0; j < 3; ++j)
                    out[row*12 + 9 + j] = Sw[lane*SSTR + j];
            }
            __syncwarp();  // scratch reads done before next tile overwrites Sw
        }
    }
}

extern "C" void kernel_launch(void* const* d_in, const int* in_sizes, int n_in,
                              void* d_out, int out_size)
{
    const float* y   = (const float*)d_in[0];
    const float* ow0 = (const float*)d_in[1];
    const float* ob0 = (const float*)d_in[2];
    const float* ow1 = (const float*)d_in[3];
    const float* ob1 = (const float*)d_in[4];
    const float* ow2 = (const float*)d_in[5];
    const float* ob2 = (const float*)d_in[6];
    const float* tw0 = (const float*)d_in[7];
    const float* tb0 = (const float*)d_in[8];
    const float* tw1 = (const float*)d_in[9];
    const float* tb1 = (const float*)d_in[10];
    const float* tw2 = (const float*)d_in[11];
    const float* tb2 = (const float*)d_in[12];
    float* out = (float*)d_out;

    const int Bn = in_sizes[0] / 64;
    const int tiles = Bn / TILE;                 // 256 for B=131072

    int sms = 148;
    cudaDeviceGetAttribute(&sms, cudaDevAttrMultiProcessorCount, 0);
    int grid = tiles < sms ? tiles : sms;

    cudaFuncSetAttribute(l2t_reg_kernel, cudaFuncAttributeMaxDynamicSharedMemorySize, SMEM_BYTES);
    l2t_reg_kernel<<<grid, NT, SMEM_BYTES>>>(y, ow0, ob0, ow1, ob1, ow2, ob2,
                                             tw0, tb0, tw1, tb1, tw2, tb2, out, tiles);
}